// round 7
// baseline (speedup 1.0000x reference)
#include <cuda_runtime.h>

#define BB 8
#define TT 512
#define DD 64
#define TILE 64
#define NT (TT / TILE)               // 8 tiles per dim
#define NPAIR (NT * (NT + 1) / 2)    // 36 upper-tri tile pairs
#define TSTR 66                       // transposed [d][row] stride (floats)

// sqrt(log2(e)): pre-scale x so exp(-(dx)^2) = ex2(-(s*dx)^2)
#define SQRT_LOG2E 1.2011224087864498f

typedef unsigned long long u64;

__device__ float g_v[BB * TT * DD];   // scratch: v = x @ W^T + b (512 KB)

// ---- f32x2 packed helpers (sm_103a) --------------------------------------
__device__ __forceinline__ u64 pack2(float lo, float hi) {
    u64 r; asm("mov.b64 %0, {%1, %2};" : "=l"(r) : "f"(lo), "f"(hi)); return r;
}
__device__ __forceinline__ void unpack2(u64 v, float& lo, float& hi) {
    asm("mov.b64 {%0, %1}, %2;" : "=f"(lo), "=f"(hi) : "l"(v));
}
__device__ __forceinline__ u64 add2(u64 a, u64 b) {
    u64 r; asm("add.rn.f32x2 %0, %1, %2;" : "=l"(r) : "l"(a), "l"(b)); return r;
}
__device__ __forceinline__ u64 fma2(u64 a, u64 b, u64 c) {
    u64 r; asm("fma.rn.f32x2 %0, %1, %2, %3;" : "=l"(r) : "l"(a), "l"(b), "l"(c)); return r;
}
// e = ex2(-(a*a)): ptxas folds the negation into the FMUL source modifier.
__device__ __forceinline__ float exp2negsq(float a) {
    float m = -a * a;
    float r; asm("ex2.approx.ftz.f32 %0, %1;" : "=f"(r) : "f"(m));
    return r;
}

// ---------------------------------------------------------------------------
// Kernel 1: v[b,t,e] = sum_d x[b,t,d] * W[e,d] + bias[e]
// 128 blocks x 256 threads, 32 rows/block; f32x2 FMAs (2x density).
// ---------------------------------------------------------------------------
#define WSTR 68
__global__ __launch_bounds__(256)
void v_kernel(const float* __restrict__ x, const float* __restrict__ W,
              const float* __restrict__ bias) {
    __shared__ float sWT[DD * WSTR];     // sWT[d*68 + e] = W[e*64 + d]
    __shared__ float sX[32 * DD];

    int tid = threadIdx.x;
    int row0 = blockIdx.x * 32;

    for (int k = tid; k < DD * DD; k += 256) {
        int e = k >> 6, d = k & 63;
        sWT[d * WSTR + e] = W[k];
    }
    for (int k = tid; k < 32 * DD; k += 256)
        sX[k] = x[row0 * DD + k];
    __syncthreads();

    int eg = tid & 15;                   // e = 4*eg .. 4*eg+3
    int rs = tid >> 4;                   // rows rs, rs+16
    float4 b4 = *(const float4*)&bias[4 * eg];
    u64 acc0a = pack2(b4.x, b4.y), acc0b = pack2(b4.z, b4.w);
    u64 acc1a = acc0a, acc1b = acc0b;

#pragma unroll 8
    for (int d = 0; d < DD; d++) {
        const float* wp = &sWT[d * WSTR + 4 * eg];
        u64 wA = *(const u64*)&wp[0];    // LDS.64 x2, conflict-free
        u64 wB = *(const u64*)&wp[2];
        float x0 = sX[rs * DD + d];
        float x1 = sX[(rs + 16) * DD + d];
        u64 x0p = pack2(x0, x0), x1p = pack2(x1, x1);
        acc0a = fma2(x0p, wA, acc0a);
        acc0b = fma2(x0p, wB, acc0b);
        acc1a = fma2(x1p, wA, acc1a);
        acc1b = fma2(x1p, wB, acc1b);
    }
    float o0, o1, o2, o3;
    unpack2(acc0a, o0, o1); unpack2(acc0b, o2, o3);
    *(float4*)&g_v[(row0 + rs) * DD + 4 * eg] = make_float4(o0, o1, o2, o3);
    unpack2(acc1a, o0, o1); unpack2(acc1b, o2, o3);
    *(float4*)&g_v[(row0 + rs + 16) * DD + 4 * eg] = make_float4(o0, o1, o2, o3);
}

// ---------------------------------------------------------------------------
// Kernel 2: pairwise RBF with (i,j) symmetry. Block = (b, upper-tri 64x64
// tile pair), 512 threads, 2x4 elems/thread, 2 CTAs/SM (regs capped 64 ->
// 32 resident warps/SM, 8/SMSP). Thread (tx,ty): i rows {ty, ty+32},
// j col-pairs {2tx,2tx+1} and {2tx+32,2tx+33}. Transposed [d][row] smem:
// conflict-free inner LDS. j staged negated: diff = one add2.
// ---------------------------------------------------------------------------
__global__ __launch_bounds__(512, 2)
void rbf_kernel(const float* __restrict__ x, float* __restrict__ out) {
    extern __shared__ float smem[];
    float* XI  = smem;                   // +s*xi   [d*66 + row]
    float* NXJ = XI  + DD * TSTR;        // -s*xj
    float* VI  = NXJ + DD * TSTR;
    float* VJ  = VI  + DD * TSTR;

    int b = blockIdx.y;
    int p = blockIdx.x;
    int ti = 0, rem = p;
    while (rem >= NT - ti) { rem -= NT - ti; ti++; }
    int tj = ti + rem;
    int i0 = ti * TILE, j0 = tj * TILE;

    int tid = threadIdx.x;
    const float* xb = x + b * TT * DD;
    const float* vb = g_v + b * TT * DD;

#pragma unroll
    for (int k = 0; k < 8; k++) {
        int idx = tid + k * 512;
        int r = idx >> 6, d = idx & 63;
        int sa = d * TSTR + r;
        XI[sa]  =  SQRT_LOG2E * xb[i0 * DD + idx];
        NXJ[sa] = -SQRT_LOG2E * xb[j0 * DD + idx];
        VI[sa]  = vb[i0 * DD + idx];
        VJ[sa]  = vb[j0 * DD + idx];
    }
    __syncthreads();

    int tx = tid & 15, ty = tid >> 4;    // ty 0..31

    u64 den[2][2], ni[2][2], nj[2][2];
#pragma unroll
    for (int r = 0; r < 2; r++)
#pragma unroll
        for (int c = 0; c < 2; c++) { den[r][c] = 0ULL; ni[r][c] = 0ULL; nj[r][c] = 0ULL; }

#pragma unroll 2
    for (int d = 0; d < DD; d++) {
        const float* XId  = XI  + d * TSTR;
        const float* VId  = VI  + d * TSTR;
        const float* NXJd = NXJ + d * TSTR;
        const float* VJd  = VJ  + d * TSTR;

        float fi[2], fv[2];
        fi[0] = XId[ty];       fi[1] = XId[ty + 32];   // broadcast LDS
        fv[0] = VId[ty];       fv[1] = VId[ty + 32];
        u64 njc[2], jvc[2];
        njc[0] = *(const u64*)&NXJd[2 * tx];            // conflict-free LDS.64
        njc[1] = *(const u64*)&NXJd[2 * tx + 32];
        jvc[0] = *(const u64*)&VJd[2 * tx];
        jvc[1] = *(const u64*)&VJd[2 * tx + 32];

#pragma unroll
        for (int r = 0; r < 2; r++) {
            u64 fid = pack2(fi[r], fi[r]);
            u64 fvd = pack2(fv[r], fv[r]);
#pragma unroll
            for (int c = 0; c < 2; c++) {
                u64 a2 = add2(fid, njc[c]);      // s*(xi - xj), 2 elems
                float a0, a1; unpack2(a2, a0, a1);
                float e0 = exp2negsq(a0);        // FMUL(-a,a) + MUFU.EX2
                float e1 = exp2negsq(a1);
                u64 e2 = pack2(e0, e1);
                den[r][c] = add2(den[r][c], e2);
                ni[r][c]  = fma2(e2, fvd, ni[r][c]);
                nj[r][c]  = fma2(e2, jvc[c], nj[r][c]);
            }
        }
    }

    float* ob = out + (size_t)b * TT * TT;

    float oi[2][2][2], oj[2][2][2];
#pragma unroll
    for (int r = 0; r < 2; r++)
#pragma unroll
        for (int c = 0; c < 2; c++) {
            float d0, d1, n0, n1, q0, q1;
            unpack2(den[r][c], d0, d1);
            unpack2(ni[r][c],  n0, n1);
            unpack2(nj[r][c],  q0, q1);
            float rc0, rc1;
            asm("rcp.approx.ftz.f32 %0, %1;" : "=f"(rc0) : "f"(d0));
            asm("rcp.approx.ftz.f32 %0, %1;" : "=f"(rc1) : "f"(d1));
            oi[r][c][0] = n0 * rc0; oi[r][c][1] = n1 * rc1;
            oj[r][c][0] = q0 * rc0; oj[r][c][1] = q1 * rc1;
        }

    // main writes: float2, coalesced across tx
#pragma unroll
    for (int r = 0; r < 2; r++) {
        int gi = i0 + ty + 32 * r;
#pragma unroll
        for (int c = 0; c < 2; c++) {
            float2 w = make_float2(oi[r][c][0], oi[r][c][1]);
            *(float2*)&ob[(size_t)gi * TT + j0 + 2 * tx + 32 * c] = w;
        }
    }

    if (ti != tj) {
        // mirror: out[b, gj, gi]
#pragma unroll
        for (int c = 0; c < 2; c++) {
#pragma unroll
            for (int e = 0; e < 2; e++) {
                int gj = j0 + 2 * tx + 32 * c + e;
                ob[(size_t)gj * TT + i0 + ty]      = oj[0][c][e];
                ob[(size_t)gj * TT + i0 + ty + 32] = oj[1][c][e];
            }
        }
    }
}

extern "C" void kernel_launch(void* const* d_in, const int* in_sizes, int n_in,
                              void* d_out, int out_size) {
    const float* x = (const float*)d_in[0];    // (8,512,64)
    const float* W = (const float*)d_in[1];    // (64,64)
    const float* bias = (const float*)d_in[2]; // (64,)
    float* out = (float*)d_out;                // (8,512,512)

    static bool attr_set = false;
    size_t smem_bytes = 4 * DD * TSTR * sizeof(float);   // 67584
    if (!attr_set) {
        cudaFuncSetAttribute(rbf_kernel,
                             cudaFuncAttributeMaxDynamicSharedMemorySize,
                             (int)smem_bytes);
        attr_set = true;
    }

    v_kernel<<<(BB * TT) / 32, 256>>>(x, W, bias);
    rbf_kernel<<<dim3(NPAIR, BB), 512, smem_bytes>>>(x, out);
}